// round 4
// baseline (speedup 1.0000x reference)
#include <cuda_runtime.h>
#include <cuda_fp16.h>

// Problem dims (fixed by dataset): N=30000, F=16, S=8, H=16, E=300000
#define NMAX   30016
#define NBLK   148
#define NTHR   512
#define NLANES (NBLK * NTHR)   // 75776

// g, j-major layout:
//   g8[n][j]  = 32B chunk: slices 0..7 for h-pair j, as 8x half2
//   gbias[n][j] = half2 (bias slice, from bk)
__device__ __half   g8[(size_t)NMAX * 128];
__device__ __half   gbias[(size_t)NMAX * 16];
__device__ float    agg_buf[(size_t)NMAX * 16];
__device__ unsigned pooled_bits[16];
__device__ unsigned bar_cnt[3];    // monotonic epoch counters (never reset)

#define FMA2(acc, a, b) \
    asm("fma.rn.f32x2 %0, %1, %2, %3;" : "=l"(acc) : "l"(a), "l"(b), "l"(acc))
#define PACK2(dst, v) \
    asm("mov.b64 %0, {%1, %1};" : "=l"(dst) : "f"(v))
#define UNPACK2(lo, hi, v) \
    asm("mov.b64 {%0, %1}, %2;" : "=f"(lo), "=f"(hi) : "l"(v))

__device__ __forceinline__ unsigned cvt_h2(unsigned long long acc)
{
    float lo, hi;
    UNPACK2(lo, hi, acc);
    __half2 h = __floats2half2_rn(lo, hi);
    return *(unsigned*)&h;
}

// Grid barrier, graph-replay safe: counter is monotonic; each arrival waits
// for the next multiple of NBLK. All NBLK blocks are co-resident (1 per SM).
__device__ __forceinline__ void gbar(int i)
{
    __syncthreads();
    if (threadIdx.x == 0) {
        __threadfence();
        unsigned old  = atomicAdd(&bar_cnt[i], 1u);
        unsigned goal = old + (NBLK - old % NBLK);
        unsigned cur;
        do {
            cur = *(volatile unsigned*)&bar_cnt[i];
            if ((int)(cur - goal) >= 0) break;
            __nanosleep(64);
        } while (1);
    }
    __syncthreads();
}

__global__ void __launch_bounds__(NTHR, 1)
fused(const float* __restrict__ x,   const float* __restrict__ e,
      const int*   __restrict__ src, const int*   __restrict__ dst,
      const float* __restrict__ Wk,  const float* __restrict__ bk,
      const float* __restrict__ Wr,  const float* __restrict__ br,
      const float* __restrict__ gamma, const float* __restrict__ beta,
      const float* __restrict__ mmean, const float* __restrict__ mvar,
      const float* __restrict__ Wd,  const float* __restrict__ bd,
      float* __restrict__ out, int N, int E)
{
    __shared__ float Ms[2560];        // [t][f][h]: t=0..7 Wk, 8 bk, 9 Wr
    __shared__ float wmax[16][16];
    __shared__ float sc_s[16], sh_s[16];

    int tid = threadIdx.x;
    int bid = blockIdx.x;
    int j   = tid & 7;                // h-pair index: h = 2j, 2j+1

    // ---------------- Phase P: per-node precompute --------------------------
    for (int i = tid; i < 2048; i += NTHR) Ms[i] = Wk[i];
    if (tid < 256) Ms[2048 + tid] = bk[tid];
    else           Ms[2304 + tid - 256] = Wr[tid - 256];
    if (bid == 0 && tid < 16) pooled_bits[tid] = 0u;
    __syncthreads();

    {
        int slot = tid >> 3;          // 0..63
        const float4* X4 = (const float4*)x;
        const unsigned long long* W2 = (const unsigned long long*)Ms;
        float br0 = br[2 * j], br1 = br[2 * j + 1];

        for (int n = bid * 64 + slot; n < N; n += NBLK * 64) {
            float4 xv[4];
#pragma unroll
            for (int q = 0; q < 4; q++) xv[q] = X4[n * 4 + q];

            unsigned long long acc[10];
#pragma unroll
            for (int t = 0; t < 10; t++) acc[t] = 0ull;

#pragma unroll
            for (int q = 0; q < 4; q++) {
                float xf[4] = { xv[q].x, xv[q].y, xv[q].z, xv[q].w };
#pragma unroll
                for (int fi = 0; fi < 4; fi++) {
                    int f = q * 4 + fi;
                    unsigned long long x2;
                    PACK2(x2, xf[fi]);
#pragma unroll
                    for (int t = 0; t < 10; t++)
                        FMA2(acc[t], x2, W2[t * 128 + f * 8 + j]);
                }
            }

            // stores: slices 0..7 -> g8 (2x uint4), slice 8 -> gbias,
            // slice 9 (+br) -> agg init
            uint4 c0 = make_uint4(cvt_h2(acc[0]), cvt_h2(acc[1]),
                                  cvt_h2(acc[2]), cvt_h2(acc[3]));
            uint4 c1 = make_uint4(cvt_h2(acc[4]), cvt_h2(acc[5]),
                                  cvt_h2(acc[6]), cvt_h2(acc[7]));
            __half* gp = g8 + (size_t)n * 128 + j * 16;
            *(uint4*)gp       = c0;
            *(uint4*)(gp + 8) = c1;
            ((unsigned*)gbias)[n * 8 + j] = cvt_h2(acc[8]);

            float lo, hi;
            UNPACK2(lo, hi, acc[9]);
            *(float2*)(agg_buf + (size_t)n * 16 + 2 * j) =
                make_float2(lo + br0, hi + br1);
        }
    }

    gbar(0);

    // ---------------- Phase E: edge gather + dot + scatter-red --------------
    {
        int E8 = E * 8;
        for (int t = bid * NTHR + tid; t < E8; t += NLANES) {
            int gid = t >> 3;         // edge id; t&7 == j

            int sn = __ldg(src + gid);
            int dn = __ldg(dst + gid);

            const float4* ep = (const float4*)e + (size_t)gid * 2;
            float4 e0 = __ldg(ep);
            float4 e1 = __ldg(ep + 1);

            const uint4* gp = (const uint4*)(g8 + (size_t)sn * 128 + j * 16);
            uint4 a = __ldg(gp);
            uint4 b = __ldg(gp + 1);
            unsigned gb = __ldg((const unsigned*)gbias + sn * 8 + j);

            float2 w0 = __half22float2(*(__half2*)&a.x);
            float2 w1 = __half22float2(*(__half2*)&a.y);
            float2 w2 = __half22float2(*(__half2*)&a.z);
            float2 w3 = __half22float2(*(__half2*)&a.w);
            float2 w4 = __half22float2(*(__half2*)&b.x);
            float2 w5 = __half22float2(*(__half2*)&b.y);
            float2 w6 = __half22float2(*(__half2*)&b.z);
            float2 w7 = __half22float2(*(__half2*)&b.w);
            float2 wb = __half22float2(*(__half2*)&gb);

            float ax = wb.x, ay = wb.y;
            ax = fmaf(e0.x, w0.x, ax);  ay = fmaf(e0.x, w0.y, ay);
            ax = fmaf(e0.y, w1.x, ax);  ay = fmaf(e0.y, w1.y, ay);
            ax = fmaf(e0.z, w2.x, ax);  ay = fmaf(e0.z, w2.y, ay);
            ax = fmaf(e0.w, w3.x, ax);  ay = fmaf(e0.w, w3.y, ay);
            ax = fmaf(e1.x, w4.x, ax);  ay = fmaf(e1.x, w4.y, ay);
            ax = fmaf(e1.y, w5.x, ax);  ay = fmaf(e1.y, w5.y, ay);
            ax = fmaf(e1.z, w6.x, ax);  ay = fmaf(e1.z, w6.y, ay);
            ax = fmaf(e1.w, w7.x, ax);  ay = fmaf(e1.w, w7.y, ay);

            float* o = agg_buf + (size_t)dn * 16 + 2 * j;
            asm volatile("red.global.add.v2.f32 [%0], {%1, %2};"
                         :: "l"(o), "f"(ax), "f"(ay) : "memory");
        }
    }

    gbar(1);

    // ---------------- Phase C: relu+BN+maxpool ------------------------------
    {
        if (tid < 16) {
            float sc = gamma[tid] * rsqrtf(mvar[tid] + 1e-3f);
            sc_s[tid] = sc;
            sh_s[tid] = beta[tid] - mmean[tid] * sc;
        }
        __syncthreads();

        int n = bid * NTHR + tid;     // NLANES >= N: single pass
        float v[16];
        if (n < N) {
            const float4* ar = (const float4*)(agg_buf + (size_t)n * 16);
#pragma unroll
            for (int q = 0; q < 4; q++) {
                float4 a = __ldcg(ar + q);
                v[4 * q + 0] = a.x; v[4 * q + 1] = a.y;
                v[4 * q + 2] = a.z; v[4 * q + 3] = a.w;
            }
#pragma unroll
            for (int h = 0; h < 16; h++)
                v[h] = fmaxf(v[h], 0.0f) * sc_s[h] + sh_s[h];
        } else {
#pragma unroll
            for (int h = 0; h < 16; h++) v[h] = -__int_as_float(0x7f800000);
        }

#pragma unroll
        for (int off = 16; off >= 1; off >>= 1) {
#pragma unroll
            for (int h = 0; h < 16; h++)
                v[h] = fmaxf(v[h], __shfl_xor_sync(0xffffffffu, v[h], off));
        }

        int wid = tid >> 5;
        if ((tid & 31) == 0) {
#pragma unroll
            for (int h = 0; h < 16; h++) wmax[wid][h] = v[h];
        }
        __syncthreads();

        if (tid < 16) {
            float m = wmax[0][tid];
#pragma unroll
            for (int w = 1; w < 16; w++) m = fmaxf(m, wmax[w][tid]);
            unsigned b = __float_as_uint(m);
            unsigned k = (b & 0x80000000u) ? ~b : (b | 0x80000000u);
            atomicMax(&pooled_bits[tid], k);
        }
    }

    gbar(2);

    // ---------------- Finalize (block 0) ------------------------------------
    if (bid == 0) {
        __shared__ float pooled[16];
        if (tid < 16) {
            unsigned k = atomicAdd(&pooled_bits[tid], 0u);
            unsigned b = (k & 0x80000000u) ? (k ^ 0x80000000u) : ~k;
            pooled[tid] = __uint_as_float(b);
        }
        __syncthreads();
        if (tid < 3) {
            float s = bd[tid];
#pragma unroll
            for (int h = 0; h < 16; h++) s += pooled[h] * Wd[h * 3 + tid];
            out[tid] = s;
        }
    }
}

// ---------------------------------------------------------------------------
extern "C" void kernel_launch(void* const* d_in, const int* in_sizes, int n_in,
                              void* d_out, int out_size)
{
    const float* x     = (const float*)d_in[0];
    const float* e     = (const float*)d_in[1];
    const int*   src   = (const int*)d_in[2];
    const int*   dst   = (const int*)d_in[3];
    const float* Wk    = (const float*)d_in[4];
    const float* bk    = (const float*)d_in[5];
    const float* Wr    = (const float*)d_in[6];
    const float* br    = (const float*)d_in[7];
    const float* gamma = (const float*)d_in[8];
    const float* beta  = (const float*)d_in[9];
    const float* mmean = (const float*)d_in[10];
    const float* mvar  = (const float*)d_in[11];
    const float* Wd    = (const float*)d_in[12];
    const float* bd    = (const float*)d_in[13];

    int N = in_sizes[0] / 16;   // F = 16
    int E = in_sizes[2];

    fused<<<NBLK, NTHR>>>(x, e, src, dst, Wk, bk, Wr, br,
                          gamma, beta, mmean, mvar, Wd, bd,
                          (float*)d_out, N, E);
}

// round 5
// speedup vs baseline: 1.7710x; 1.7710x over previous
#include <cuda_runtime.h>
#include <cuda_fp16.h>

// Problem dims (fixed by dataset): N=30000, F=16, S=8, H=16, E=300000
#define NMAX 30016

// g, j-major layout:
//   g8[n*128 + j*16 .. +15] : 16 halves = slices 0..7 for h-pair j (2 x uint4)
//   gbias[n*8 + j]          : half2 bias slice (from bk)
__device__ __half   g8[(size_t)NMAX * 128];
__device__ unsigned gbias[(size_t)NMAX * 8];
__device__ float    agg_buf[(size_t)NMAX * 16];
__device__ unsigned pooled_bits[16];
__device__ unsigned finish_count;

#define FMA2(acc, a, b) \
    asm("fma.rn.f32x2 %0, %1, %2, %3;" : "=l"(acc) : "l"(a), "l"(b), "l"(acc))
#define PACK2(dst, v) \
    asm("mov.b64 %0, {%1, %1};" : "=l"(dst) : "f"(v))
#define UNPACK2(lo, hi, v) \
    asm("mov.b64 {%0, %1}, %2;" : "=f"(lo), "=f"(hi) : "l"(v))

__device__ __forceinline__ unsigned cvt_h2(unsigned long long acc)
{
    float lo, hi;
    UNPACK2(lo, hi, acc);
    __half2 h = __floats2half2_rn(lo, hi);
    return *(unsigned*)&h;
}

// ---------------------------------------------------------------------------
// Kernel P: per-node precompute. Thread = (node, j-pair); block 256 = 32 nodes.
// 10 independent f32x2 accumulator chains; weights broadcast from smem (LDS.64).
// Outputs j-major g8 (2x STG.128 per (n,j)), gbias, and agg init (x@Wr + br).
// ---------------------------------------------------------------------------
__global__ void __launch_bounds__(256) node_pre(const float* __restrict__ x,
                                                const float* __restrict__ Wk,
                                                const float* __restrict__ bk,
                                                const float* __restrict__ Wr,
                                                const float* __restrict__ br,
                                                int N)
{
    __shared__ float Ms[2560];   // [t][f][h], t=0..7 Wk, t=8 bk, t=9 Wr

    int tid = threadIdx.x;
    for (int i = tid; i < 2048; i += 256) Ms[i] = Wk[i];
    Ms[2048 + tid] = bk[tid];
    Ms[2304 + tid] = Wr[tid];
    if (blockIdx.x == 0) {
        if (tid < 16) pooled_bits[tid] = 0u;
        if (tid == 0) finish_count = 0u;
    }
    __syncthreads();

    int j = tid & 7;
    int n = blockIdx.x * 32 + (tid >> 3);
    if (n >= N) return;

    // x row into registers (4 x LDG.128, broadcast across the 8 j-lanes)
    const float4* X4 = (const float4*)x + (size_t)n * 4;
    float4 xv0 = __ldg(X4 + 0);
    float4 xv1 = __ldg(X4 + 1);
    float4 xv2 = __ldg(X4 + 2);
    float4 xv3 = __ldg(X4 + 3);
    float xf[16] = { xv0.x, xv0.y, xv0.z, xv0.w,  xv1.x, xv1.y, xv1.z, xv1.w,
                     xv2.x, xv2.y, xv2.z, xv2.w,  xv3.x, xv3.y, xv3.z, xv3.w };

    const unsigned long long* W2 = (const unsigned long long*)Ms;

    unsigned long long acc[10];
#pragma unroll
    for (int t = 0; t < 10; t++) acc[t] = 0ull;

#pragma unroll
    for (int f = 0; f < 16; f++) {
        unsigned long long x2;
        PACK2(x2, xf[f]);
#pragma unroll
        for (int t = 0; t < 10; t++)
            FMA2(acc[t], x2, W2[t * 128 + f * 8 + j]);
    }

    // j-major stores: slices 0..7 -> two contiguous uint4
    uint4 c0 = make_uint4(cvt_h2(acc[0]), cvt_h2(acc[1]),
                          cvt_h2(acc[2]), cvt_h2(acc[3]));
    uint4 c1 = make_uint4(cvt_h2(acc[4]), cvt_h2(acc[5]),
                          cvt_h2(acc[6]), cvt_h2(acc[7]));
    __half* gp = g8 + (size_t)n * 128 + j * 16;
    *(uint4*)gp       = c0;
    *(uint4*)(gp + 8) = c1;
    gbias[n * 8 + j] = cvt_h2(acc[8]);

    float lo, hi;
    UNPACK2(lo, hi, acc[9]);
    *(float2*)(agg_buf + (size_t)n * 16 + 2 * j) =
        make_float2(lo + br[2 * j], hi + br[2 * j + 1]);
}

// ---------------------------------------------------------------------------
// Kernel E: per-edge gather (j-major fp16 g) + dot + vector red scatter.
// 8 lanes per edge, lane j owns h = {2j, 2j+1}. Gather = 2x LDG.128 + LDG.32.
// ---------------------------------------------------------------------------
__global__ void __launch_bounds__(256) edge_kernel(const float* __restrict__ e,
                                                   const int* __restrict__ src,
                                                   const int* __restrict__ dst,
                                                   int E)
{
    int t = blockIdx.x * 256 + threadIdx.x;
    int gid = t >> 3;
    if (gid >= E) return;
    int j = t & 7;

    int sn = __ldg(src + gid);
    int dn = __ldg(dst + gid);

    const float4* ep = (const float4*)e + (size_t)gid * 2;
    float4 e0 = __ldg(ep);
    float4 e1 = __ldg(ep + 1);

    const uint4* gp = (const uint4*)(g8 + (size_t)sn * 128 + j * 16);
    uint4 a = __ldg(gp);
    uint4 b = __ldg(gp + 1);
    unsigned gb = __ldg(gbias + sn * 8 + j);

    float2 w0 = __half22float2(*(__half2*)&a.x);
    float2 w1 = __half22float2(*(__half2*)&a.y);
    float2 w2 = __half22float2(*(__half2*)&a.z);
    float2 w3 = __half22float2(*(__half2*)&a.w);
    float2 w4 = __half22float2(*(__half2*)&b.x);
    float2 w5 = __half22float2(*(__half2*)&b.y);
    float2 w6 = __half22float2(*(__half2*)&b.z);
    float2 w7 = __half22float2(*(__half2*)&b.w);
    float2 wb = __half22float2(*(__half2*)&gb);

    float ax = wb.x, ay = wb.y;
    ax = fmaf(e0.x, w0.x, ax);  ay = fmaf(e0.x, w0.y, ay);
    ax = fmaf(e0.y, w1.x, ax);  ay = fmaf(e0.y, w1.y, ay);
    ax = fmaf(e0.z, w2.x, ax);  ay = fmaf(e0.z, w2.y, ay);
    ax = fmaf(e0.w, w3.x, ax);  ay = fmaf(e0.w, w3.y, ay);
    ax = fmaf(e1.x, w4.x, ax);  ay = fmaf(e1.x, w4.y, ay);
    ax = fmaf(e1.y, w5.x, ax);  ay = fmaf(e1.y, w5.y, ay);
    ax = fmaf(e1.z, w6.x, ax);  ay = fmaf(e1.z, w6.y, ay);
    ax = fmaf(e1.w, w7.x, ax);  ay = fmaf(e1.w, w7.y, ay);

    float* o = agg_buf + (size_t)dn * 16 + 2 * j;
    asm volatile("red.global.add.v2.f32 [%0], {%1, %2};"
                 :: "l"(o), "f"(ax), "f"(ay) : "memory");
}

// ---------------------------------------------------------------------------
// Kernel C: relu + BN + block max-reduce + atomicMax; LAST block finalizes.
// ---------------------------------------------------------------------------
__global__ void __launch_bounds__(256) node_post(const float* __restrict__ gamma,
                                                 const float* __restrict__ beta,
                                                 const float* __restrict__ mmean,
                                                 const float* __restrict__ mvar,
                                                 const float* __restrict__ Wd,
                                                 const float* __restrict__ bd,
                                                 float* __restrict__ out,
                                                 int N)
{
    __shared__ float wmax[8][16];
    __shared__ float sc_s[16], sh_s[16];
    __shared__ bool is_last;
    int n = blockIdx.x * 256 + threadIdx.x;

    if (threadIdx.x < 16) {
        float sc = gamma[threadIdx.x] * rsqrtf(mvar[threadIdx.x] + 1e-3f);
        sc_s[threadIdx.x] = sc;
        sh_s[threadIdx.x] = beta[threadIdx.x] - mmean[threadIdx.x] * sc;
    }
    __syncthreads();

    float v[16];
    if (n < N) {
        const float4* ar = (const float4*)(agg_buf + (size_t)n * 16);
#pragma unroll
        for (int q = 0; q < 4; q++) {
            float4 a = __ldcg(ar + q);
            v[4 * q + 0] = a.x; v[4 * q + 1] = a.y;
            v[4 * q + 2] = a.z; v[4 * q + 3] = a.w;
        }
#pragma unroll
        for (int h = 0; h < 16; h++)
            v[h] = fmaxf(v[h], 0.0f) * sc_s[h] + sh_s[h];
    } else {
#pragma unroll
        for (int h = 0; h < 16; h++) v[h] = -__int_as_float(0x7f800000);
    }

#pragma unroll
    for (int off = 16; off >= 1; off >>= 1) {
#pragma unroll
        for (int h = 0; h < 16; h++)
            v[h] = fmaxf(v[h], __shfl_xor_sync(0xffffffffu, v[h], off));
    }

    int wid = threadIdx.x >> 5;
    if ((threadIdx.x & 31) == 0) {
#pragma unroll
        for (int h = 0; h < 16; h++) wmax[wid][h] = v[h];
    }
    __syncthreads();

    if (threadIdx.x < 16) {
        float m = wmax[0][threadIdx.x];
#pragma unroll
        for (int w = 1; w < 8; w++) m = fmaxf(m, wmax[w][threadIdx.x]);
        unsigned b = __float_as_uint(m);
        unsigned k = (b & 0x80000000u) ? ~b : (b | 0x80000000u);
        atomicMax(&pooled_bits[threadIdx.x], k);
    }

    __threadfence();
    if (threadIdx.x == 0) {
        unsigned c = atomicAdd(&finish_count, 1u);
        is_last = (c == gridDim.x - 1);
    }
    __syncthreads();
    if (!is_last) return;

    __threadfence();
    __shared__ float pooled[16];
    if (threadIdx.x < 16) {
        unsigned k = atomicAdd(&pooled_bits[threadIdx.x], 0u);
        unsigned b = (k & 0x80000000u) ? (k ^ 0x80000000u) : ~k;
        pooled[threadIdx.x] = __uint_as_float(b);
    }
    __syncthreads();
    if (threadIdx.x < 3) {
        float s = bd[threadIdx.x];
#pragma unroll
        for (int h = 0; h < 16; h++) s += pooled[h] * Wd[h * 3 + threadIdx.x];
        out[threadIdx.x] = s;
    }
}

// ---------------------------------------------------------------------------
extern "C" void kernel_launch(void* const* d_in, const int* in_sizes, int n_in,
                              void* d_out, int out_size)
{
    const float* x     = (const float*)d_in[0];
    const float* e     = (const float*)d_in[1];
    const int*   src   = (const int*)d_in[2];
    const int*   dst   = (const int*)d_in[3];
    const float* Wk    = (const float*)d_in[4];
    const float* bk    = (const float*)d_in[5];
    const float* Wr    = (const float*)d_in[6];
    const float* br    = (const float*)d_in[7];
    const float* gamma = (const float*)d_in[8];
    const float* beta  = (const float*)d_in[9];
    const float* mmean = (const float*)d_in[10];
    const float* mvar  = (const float*)d_in[11];
    const float* Wd    = (const float*)d_in[12];
    const float* bd    = (const float*)d_in[13];

    int N = in_sizes[0] / 16;   // F = 16
    int E = in_sizes[2];

    node_pre<<<(N + 31) / 32, 256>>>(x, Wk, bk, Wr, br, N);
    edge_kernel<<<(E * 8 + 255) / 256, 256>>>(e, src, dst, E);
    node_post<<<(N + 255) / 256, 256>>>(gamma, beta, mmean, mvar, Wd, bd,
                                        (float*)d_out, N);
}

// round 7
// speedup vs baseline: 2.1682x; 1.2243x over previous
#include <cuda_runtime.h>
#include <cuda_fp16.h>

// Problem dims (fixed by dataset): N=30000, F=16, S=8, H=16, E=300000
#define NMAX 30080   // 235 blocks * 128 nodes

// g, j-major layout (uint view): gu[n*64 + j*8 + t] = half2 for (h=2j,2j+1), slice t
__device__ __half   g8[(size_t)NMAX * 128];
__device__ unsigned gbias[(size_t)NMAX * 8];
__device__ float    agg_buf[(size_t)NMAX * 16];
__device__ unsigned pooled_bits[16];
__device__ unsigned finish_count;

#define SLAB_STRIDE 68   // uints per node row in staging slab (>=64, mult of 4)

__device__ __forceinline__ void mma16816(float d[4],
    unsigned a0, unsigned a1, unsigned a2, unsigned a3,
    unsigned b0, unsigned b1)
{
    float z = 0.0f;
    asm("mma.sync.aligned.m16n8k16.row.col.f32.f16.f16.f32 "
        "{%0,%1,%2,%3}, {%4,%5,%6,%7}, {%8,%9}, {%10,%11,%12,%13};"
        : "=f"(d[0]), "=f"(d[1]), "=f"(d[2]), "=f"(d[3])
        : "r"(a0), "r"(a1), "r"(a2), "r"(a3), "r"(b0), "r"(b1),
          "f"(z), "f"(z), "f"(z), "f"(z));
}

__device__ __forceinline__ unsigned f2h2(float lo, float hi)
{
    __half2 h = __floats2half2_rn(lo, hi);
    return *(unsigned*)&h;
}

// ---------------------------------------------------------------------------
// Kernel P (HMMA): g[N x 160] = x[N x 16] @ Wtilde[16 x 160], fp16 in/fp32 acc.
//   Wtilde cols c = t*16+h:  t<8 -> Wk[t*256+f*16+h], t=8 -> bk, t=9 -> Wr.
// Block = 256 thr = 8 warps; warp computes a 16-node slab (all 160 outputs)
// with 20 m16n8k16 MMAs. B-frags persistent in regs; A-frags direct from x.
// Slices 0..7 staged in padded smem then flushed as coalesced STG.128.
// ---------------------------------------------------------------------------
__global__ void __launch_bounds__(256) node_pre(const float* __restrict__ x,
                                                const float* __restrict__ Wk,
                                                const float* __restrict__ bk,
                                                const float* __restrict__ Wr,
                                                const float* __restrict__ br,
                                                int N)
{
    __shared__ __half Whs[160 * 18];                 // [c][f], stride 18 (pad)
    __shared__ unsigned slab[8 * 16 * SLAB_STRIDE];  // per warp: 16 rows x 68

    int tid = threadIdx.x;
    // stage + convert weights: c = i>>4 (0..159), f = i&15
    for (int i = tid; i < 2560; i += 256) {
        int c = i >> 4, f = i & 15;
        int t = c >> 4, h = c & 15;
        float v = (t < 8) ? Wk[t * 256 + f * 16 + h]
                : (t == 8) ? bk[f * 16 + h] : Wr[f * 16 + h];
        Whs[c * 18 + f] = __float2half_rn(v);
    }
    if (blockIdx.x == 0) {
        if (tid < 16) pooled_bits[tid] = 0u;
        if (tid == 0) finish_count = 0u;
    }
    __syncthreads();

    int w = tid >> 5;              // warp 0..7
    int l = tid & 31;
    int r = l >> 2;                // lane group: 0..7 (row / B-col)
    int m = l & 3;                 // thread-in-group: 0..3
    int n0 = (blockIdx.x * 8 + w) * 16;

    // B-fragments: tile nt covers cols 8nt..8nt+7; lane's col c = 8nt + r.
    // b0 = Wtilde[f=2m,2m+1][c], b1 = Wtilde[f=2m+8,2m+9][c]
    unsigned bfr[20][2];
#pragma unroll
    for (int nt = 0; nt < 20; nt++) {
        int c = nt * 8 + r;
        bfr[nt][0] = *(const unsigned*)&Whs[c * 18 + 2 * m];
        bfr[nt][1] = *(const unsigned*)&Whs[c * 18 + 2 * m + 8];
    }

    // A-fragments from global x (row-major [n][16] fp32)
    int na = n0 + r, nb = n0 + r + 8;
    int nac = (na < N) ? na : N - 1;
    int nbc = (nb < N) ? nb : N - 1;
    const float2* X2 = (const float2*)x;
    float2 xa0 = __ldg(X2 + (size_t)nac * 8 + m);
    float2 xa2 = __ldg(X2 + (size_t)nac * 8 + m + 4);
    float2 xa1 = __ldg(X2 + (size_t)nbc * 8 + m);
    float2 xa3 = __ldg(X2 + (size_t)nbc * 8 + m + 4);
    unsigned a0 = f2h2(xa0.x, xa0.y);
    unsigned a1 = f2h2(xa1.x, xa1.y);
    unsigned a2 = f2h2(xa2.x, xa2.y);
    unsigned a3 = f2h2(xa3.x, xa3.y);

    unsigned* sw = slab + w * 16 * SLAB_STRIDE;
    float br0 = br[2 * m], br1 = br[2 * m + 1];
    float br8 = br[8 + 2 * m], br9 = br[9 + 2 * m];

#pragma unroll
    for (int nt = 0; nt < 20; nt++) {
        float d[4];
        mma16816(d, a0, a1, a2, a3, bfr[nt][0], bfr[nt][1]);
        // lane owns cols c = nt*8 + 2m (+1): j = m + 4*(nt&1), t = nt>>1
        int j = m + 4 * (nt & 1);
        if (nt < 16) {
            int t = nt >> 1;
            sw[r * SLAB_STRIDE + j * 8 + t]       = f2h2(d[0], d[1]);
            sw[(r + 8) * SLAB_STRIDE + j * 8 + t] = f2h2(d[2], d[3]);
        } else if (nt < 18) {            // t = 8: bias slice
            if (na < N) gbias[na * 8 + j] = f2h2(d[0], d[1]);
            if (nb < N) gbias[nb * 8 + j] = f2h2(d[2], d[3]);
        } else {                         // t = 9: agg init = x@Wr + br
            float c0 = (nt & 1) ? br8 : br0;
            float c1 = (nt & 1) ? br9 : br1;
            if (na < N)
                *(float2*)(agg_buf + (size_t)na * 16 + 2 * j) =
                    make_float2(d[0] + c0, d[1] + c1);
            if (nb < N)
                *(float2*)(agg_buf + (size_t)nb * 16 + 2 * j) =
                    make_float2(d[2] + c0, d[3] + c1);
        }
    }
    __syncwarp();

    // flush slab -> g8: 16 nodes x 16 uint4-chunks = 256 chunks, 8 passes
#pragma unroll
    for (int p = 0; p < 8; p++) {
        int id = p * 32 + l;
        int q  = id & 1;           // which uint4 of the (n,j) pair
        int jj = (id >> 1) & 7;
        int nn = id >> 4;          // 0..15
        int n  = n0 + nn;
        if (n >= N) continue;
        unsigned* s = sw + nn * SLAB_STRIDE + jj * 8 + q * 4;
        uint4 v = make_uint4(s[0], s[1], s[2], s[3]);
        *(uint4*)(g8 + (size_t)n * 128 + jj * 16 + q * 8) = v;
    }
}

// ---------------------------------------------------------------------------
// Kernel E: per-edge gather (j-major fp16 g) + dot + vector red scatter.
// 8 lanes per edge, lane j owns h = {2j, 2j+1}. Gather = 2x LDG.128 + LDG.32.
// ---------------------------------------------------------------------------
__global__ void __launch_bounds__(256) edge_kernel(const float* __restrict__ e,
                                                   const int* __restrict__ src,
                                                   const int* __restrict__ dst,
                                                   int E)
{
    int t = blockIdx.x * 256 + threadIdx.x;
    int gid = t >> 3;
    if (gid >= E) return;
    int j = t & 7;

    int sn = __ldg(src + gid);
    int dn = __ldg(dst + gid);

    const float4* ep = (const float4*)e + (size_t)gid * 2;
    float4 e0 = __ldg(ep);
    float4 e1 = __ldg(ep + 1);

    const uint4* gp = (const uint4*)(g8 + (size_t)sn * 128 + j * 16);
    uint4 a = __ldg(gp);
    uint4 b = __ldg(gp + 1);
    unsigned gb = __ldg(gbias + sn * 8 + j);

    float2 w0 = __half22float2(*(__half2*)&a.x);
    float2 w1 = __half22float2(*(__half2*)&a.y);
    float2 w2 = __half22float2(*(__half2*)&a.z);
    float2 w3 = __half22float2(*(__half2*)&a.w);
    float2 w4 = __half22float2(*(__half2*)&b.x);
    float2 w5 = __half22float2(*(__half2*)&b.y);
    float2 w6 = __half22float2(*(__half2*)&b.z);
    float2 w7 = __half22float2(*(__half2*)&b.w);
    float2 wb = __half22float2(*(__half2*)&gb);

    float ax = wb.x, ay = wb.y;
    ax = fmaf(e0.x, w0.x, ax);  ay = fmaf(e0.x, w0.y, ay);
    ax = fmaf(e0.y, w1.x, ax);  ay = fmaf(e0.y, w1.y, ay);
    ax = fmaf(e0.z, w2.x, ax);  ay = fmaf(e0.z, w2.y, ay);
    ax = fmaf(e0.w, w3.x, ax);  ay = fmaf(e0.w, w3.y, ay);
    ax = fmaf(e1.x, w4.x, ax);  ay = fmaf(e1.x, w4.y, ay);
    ax = fmaf(e1.y, w5.x, ax);  ay = fmaf(e1.y, w5.y, ay);
    ax = fmaf(e1.z, w6.x, ax);  ay = fmaf(e1.z, w6.y, ay);
    ax = fmaf(e1.w, w7.x, ax);  ay = fmaf(e1.w, w7.y, ay);

    float* o = agg_buf + (size_t)dn * 16 + 2 * j;
    asm volatile("red.global.add.v2.f32 [%0], {%1, %2};"
                 :: "l"(o), "f"(ax), "f"(ay) : "memory");
}

// ---------------------------------------------------------------------------
// Kernel C: relu + BN + block max-reduce + atomicMax; LAST block finalizes.
// ---------------------------------------------------------------------------
__global__ void __launch_bounds__(256) node_post(const float* __restrict__ gamma,
                                                 const float* __restrict__ beta,
                                                 const float* __restrict__ mmean,
                                                 const float* __restrict__ mvar,
                                                 const float* __restrict__ Wd,
                                                 const float* __restrict__ bd,
                                                 float* __restrict__ out,
                                                 int N)
{
    __shared__ float wmax[8][16];
    __shared__ float sc_s[16], sh_s[16];
    __shared__ bool is_last;
    int n = blockIdx.x * 256 + threadIdx.x;

    if (threadIdx.x < 16) {
        float sc = gamma[threadIdx.x] * rsqrtf(mvar[threadIdx.x] + 1e-3f);
        sc_s[threadIdx.x] = sc;
        sh_s[threadIdx.x] = beta[threadIdx.x] - mmean[threadIdx.x] * sc;
    }
    __syncthreads();

    float v[16];
    if (n < N) {
        const float4* ar = (const float4*)(agg_buf + (size_t)n * 16);
#pragma unroll
        for (int q = 0; q < 4; q++) {
            float4 a = __ldcg(ar + q);
            v[4 * q + 0] = a.x; v[4 * q + 1] = a.y;
            v[4 * q + 2] = a.z; v[4 * q + 3] = a.w;
        }
#pragma unroll
        for (int h = 0; h < 16; h++)
            v[h] = fmaxf(v[h], 0.0f) * sc_s[h] + sh_s[h];
    } else {
#pragma unroll
        for (int h = 0; h < 16; h++) v[h] = -__int_as_float(0x7f800000);
    }

#pragma unroll
    for (int off = 16; off >= 1; off >>= 1) {
#pragma unroll
        for (int h = 0; h < 16; h++)
            v[h] = fmaxf(v[h], __shfl_xor_sync(0xffffffffu, v[h], off));
    }

    int wid = threadIdx.x >> 5;
    if ((threadIdx.x & 31) == 0) {
#pragma unroll
        for (int h = 0; h < 16; h++) wmax[wid][h] = v[h];
    }
    __syncthreads();

    if (threadIdx.x < 16) {
        float m = wmax[0][threadIdx.x];
#pragma unroll
        for (int w2 = 1; w2 < 8; w2++) m = fmaxf(m, wmax[w2][threadIdx.x]);
        unsigned b = __float_as_uint(m);
        unsigned k = (b & 0x80000000u) ? ~b : (b | 0x80000000u);
        atomicMax(&pooled_bits[threadIdx.x], k);
    }

    __threadfence();
    if (threadIdx.x == 0) {
        unsigned c = atomicAdd(&finish_count, 1u);
        is_last = (c == gridDim.x - 1);
    }
    __syncthreads();
    if (!is_last) return;

    __threadfence();
    __shared__ float pooled[16];
    if (threadIdx.x < 16) {
        unsigned k = atomicAdd(&pooled_bits[threadIdx.x], 0u);
        unsigned b = (k & 0x80000000u) ? (k ^ 0x80000000u) : ~k;
        pooled[threadIdx.x] = __uint_as_float(b);
    }
    __syncthreads();
    if (threadIdx.x < 3) {
        float s = bd[threadIdx.x];
#pragma unroll
        for (int h = 0; h < 16; h++) s += pooled[h] * Wd[h * 3 + threadIdx.x];
        out[threadIdx.x] = s;
    }
}

// ---------------------------------------------------------------------------
extern "C" void kernel_launch(void* const* d_in, const int* in_sizes, int n_in,
                              void* d_out, int out_size)
{
    const float* x     = (const float*)d_in[0];
    const float* e     = (const float*)d_in[1];
    const int*   src   = (const int*)d_in[2];
    const int*   dst   = (const int*)d_in[3];
    const float* Wk    = (const float*)d_in[4];
    const float* bk    = (const float*)d_in[5];
    const float* Wr    = (const float*)d_in[6];
    const float* br    = (const float*)d_in[7];
    const float* gamma = (const float*)d_in[8];
    const float* beta  = (const float*)d_in[9];
    const float* mmean = (const float*)d_in[10];
    const float* mvar  = (const float*)d_in[11];
    const float* Wd    = (const float*)d_in[12];
    const float* bd    = (const float*)d_in[13];

    int N = in_sizes[0] / 16;   // F = 16
    int E = in_sizes[2];

    node_pre<<<(N + 127) / 128, 256>>>(x, Wk, bk, Wr, br, N);
    edge_kernel<<<(E * 8 + 255) / 256, 256>>>(e, src, dst, E);
    node_post<<<(N + 255) / 256, 256>>>(gamma, beta, mmean, mvar, Wd, bd,
                                        (float*)d_out, N);
}